// round 4
// baseline (speedup 1.0000x reference)
#include <cuda_runtime.h>
#include <cuda_bf16.h>
#include <cstdint>

// ---------------------------------------------------------------------------
// FeatherNet via warp-level mma.sync tf32 (generic PTX):
//   Vf = V1@V2 ; h1 = relu(x W1^T + b1); h2 = relu(h1 W2^T + b2); out = h2 W3^T + b3
// All 4 GEMMs NT: C[M,N] = A[M,K] * B[N,K]^T.
// R4: 3-stage cp.async ring, single __syncthreads per stage.
// ---------------------------------------------------------------------------

#define SIZE_N 5794
#define SIZE_M 2897
#define K_PAD  2912        // 91 * 32
#define BATCH  4096
#define D_IN   2048
#define D_H    4096
#define D_OUT  2048

#define OFF_W1 0
#define OFF_B1 8388608
#define OFF_W2 8392704
#define OFF_B2 25169920
#define OFF_W3 25174016
#define OFF_B3 33562624

__device__ __align__(256) float g_V1r[(size_t)SIZE_N * K_PAD];
__device__ __align__(256) float g_V2T[(size_t)SIZE_N * K_PAD];
__device__ __align__(256) float g_xr [(size_t)BATCH * D_IN];
__device__ __align__(256) float g_Vf [(size_t)SIZE_N * SIZE_N];
__device__ __align__(256) float g_h1 [(size_t)BATCH * D_H];
__device__ __align__(256) float g_h2 [(size_t)BATCH * D_H];

// ============================ helpers =======================================

__device__ __forceinline__ float rna_tf32(float v) {
    uint32_t u;
    asm("cvt.rna.tf32.f32 %0, %1;" : "=r"(u) : "f"(v));
    return __uint_as_float(u);
}

__device__ __forceinline__ uint32_t smem_u32(const void* p) {
    uint32_t a;
    asm("{ .reg .u64 t; cvta.to.shared.u64 t, %1; cvt.u32.u64 %0, t; }"
        : "=r"(a) : "l"(p));
    return a;
}

__device__ __forceinline__ void cp_async16(uint32_t dst, const void* src, bool valid) {
    int sz = valid ? 16 : 0;
    asm volatile("cp.async.cg.shared.global [%0], [%1], 16, %2;"
                 :: "r"(dst), "l"(src), "r"(sz) : "memory");
}
#define CP_COMMIT()  asm volatile("cp.async.commit_group;" ::: "memory")
#define CP_WAIT_1()  asm volatile("cp.async.wait_group 1;" ::: "memory")

__device__ __forceinline__ void mma_tf32(float4& d, const uint32_t* a, const uint32_t* b) {
    asm volatile(
        "mma.sync.aligned.m16n8k8.row.col.f32.tf32.tf32.f32 "
        "{%0,%1,%2,%3}, {%4,%5,%6,%7}, {%8,%9}, {%0,%1,%2,%3};"
        : "+f"(d.x), "+f"(d.y), "+f"(d.z), "+f"(d.w)
        : "r"(a[0]), "r"(a[1]), "r"(a[2]), "r"(a[3]), "r"(b[0]), "r"(b[1]));
}

// smem: tile rows of 32 floats (128B), 16B groups XOR-swizzled by row.
__device__ __forceinline__ int sw(int row, int k) {
    return row * 32 + ((((k >> 2) ^ row) & 7) << 2) + (k & 3);
}

// ============================ GEMM kernel ===================================
// 128x128 CTA tile, BK=32, 8 warps (2M x 4N), warp tile 64x32, 3-stage ring.

#define A_TILE_F 4096          // 128 * 32 floats
#define STAGE_F  8192          // A + B
#define NST      3
#define SMEM_BYTES (NST * STAGE_F * 4)

template<bool BIAS, bool RELU, bool ROUND>
__global__ __launch_bounds__(256, 2)
void gemm_mma(const float* __restrict__ A, const float* __restrict__ B,
              const float* __restrict__ bias, float* __restrict__ C,
              int M, int N, int K, int lda, int ldb, int ldc)
{
    extern __shared__ float smf[];
    const uint32_t smem_base = smem_u32(smf);

    const int tid = threadIdx.x;
    const int wid = tid >> 5;
    const int lid = tid & 31;
    const int r   = lid >> 2;     // 0..7
    const int c   = lid & 3;      // 0..3
    const int bm  = blockIdx.y * 128;
    const int bn  = blockIdx.x * 128;
    const int m0  = (wid & 1) * 64;
    const int n0  = (wid >> 1) * 32;

    int lrowA[4], lcgA[4];
#pragma unroll
    for (int i = 0; i < 4; i++) {
        int q = tid + i * 256;
        lrowA[i] = q >> 3;
        lcgA[i]  = q & 7;
    }

    float4 acc[4][4];
#pragma unroll
    for (int i = 0; i < 4; i++)
#pragma unroll
        for (int j = 0; j < 4; j++) acc[i][j] = make_float4(0.f, 0.f, 0.f, 0.f);

    const int T = K >> 5;   // K / 32

    auto load_stage = [&](int t, int buf) {
        const int kblk = t * 32;
        uint32_t sA = smem_base + (uint32_t)(buf * STAGE_F) * 4;
        uint32_t sB = sA + A_TILE_F * 4;
#pragma unroll
        for (int i = 0; i < 4; i++) {
            int row = lrowA[i], cg = lcgA[i];
            int gm = bm + row;
            bool v = gm < M;
            const float* src = A + (size_t)(v ? gm : 0) * lda + kblk + cg * 4;
            cp_async16(sA + (uint32_t)(sw(row, cg * 4)) * 4, src, v);
        }
#pragma unroll
        for (int i = 0; i < 4; i++) {
            int row = lrowA[i], cg = lcgA[i];
            int gn = bn + row;
            bool v = gn < N;
            const float* src = B + (size_t)(v ? gn : 0) * ldb + kblk + cg * 4;
            cp_async16(sB + (uint32_t)(sw(row, cg * 4)) * 4, src, v);
        }
        CP_COMMIT();
    };

    // prologue: 2 stages in flight
    load_stage(0, 0);
    if (T > 1) load_stage(1, 1); else CP_COMMIT();

    int buf = 0;
    for (int t = 0; t < T; t++) {
        CP_WAIT_1();             // stage t resident (one group may remain in flight)
        __syncthreads();         // make stage t visible to all warps; also protects
                                 // buffer (t+2)%NST which finished computing at t-1

        if (t + 2 < T) load_stage(t + 2, (t + 2) % NST);
        else CP_COMMIT();        // keep group accounting exact

        const float* As = smf + buf * STAGE_F;
        const float* Bs = As + A_TILE_F;
        const uint32_t* Asu = (const uint32_t*)As;
        const uint32_t* Bsu = (const uint32_t*)Bs;

#pragma unroll
        for (int kc = 0; kc < 4; kc++) {
            const int k0 = kc * 8;
            uint32_t af[4][4], bf[4][2];
#pragma unroll
            for (int i = 0; i < 4; i++) {
                int R = m0 + i * 16 + r;
                af[i][0] = Asu[sw(R,     k0 + c)];
                af[i][1] = Asu[sw(R + 8, k0 + c)];
                af[i][2] = Asu[sw(R,     k0 + c + 4)];
                af[i][3] = Asu[sw(R + 8, k0 + c + 4)];
            }
#pragma unroll
            for (int j = 0; j < 4; j++) {
                int Rb = n0 + j * 8 + r;
                bf[j][0] = Bsu[sw(Rb, k0 + c)];
                bf[j][1] = Bsu[sw(Rb, k0 + c + 4)];
            }
#pragma unroll
            for (int i = 0; i < 4; i++)
#pragma unroll
                for (int j = 0; j < 4; j++)
                    mma_tf32(acc[i][j], af[i], bf[j]);
        }

        buf++;
        if (buf == NST) buf = 0;
    }

    // ---- epilogue ----------------------------------------------------------
#pragma unroll
    for (int i = 0; i < 4; i++) {
        int gm0 = bm + m0 + i * 16 + r;
#pragma unroll
        for (int j = 0; j < 4; j++) {
            int gn = bn + n0 + j * 8 + 2 * c;
            if (gn >= N) continue;
            float b0 = 0.f, b1 = 0.f;
            if (BIAS) { b0 = __ldg(&bias[gn]); b1 = __ldg(&bias[gn + 1]); }
            float4 v = acc[i][j];
            float x0 = v.x + b0, x1 = v.y + b1;
            float y0 = v.z + b0, y1 = v.w + b1;
            if (RELU) {
                x0 = fmaxf(x0, 0.f); x1 = fmaxf(x1, 0.f);
                y0 = fmaxf(y0, 0.f); y1 = fmaxf(y1, 0.f);
            }
            if (ROUND) {
                x0 = rna_tf32(x0); x1 = rna_tf32(x1);
                y0 = rna_tf32(y0); y1 = rna_tf32(y1);
            }
            if (gm0 < M)
                *(float2*)(&C[(size_t)gm0 * ldc + gn]) = make_float2(x0, x1);
            if (gm0 + 8 < M)
                *(float2*)(&C[(size_t)(gm0 + 8) * ldc + gn]) = make_float2(y0, y1);
        }
    }
}

// ============================ prep kernels ==================================

__global__ void round_pad_kernel(const float* __restrict__ src, float* __restrict__ dst,
                                 int rows, int cols, int dstride)
{
    int total = rows * dstride;
    for (int i = blockIdx.x * blockDim.x + threadIdx.x; i < total; i += gridDim.x * blockDim.x) {
        int rr = i / dstride, cc = i - rr * dstride;
        float v = 0.0f;
        if (cc < cols) v = rna_tf32(src[(size_t)rr * cols + cc]);
        dst[i] = v;
    }
}

__global__ void transpose_round_kernel(const float* __restrict__ src, float* __restrict__ dst)
{
    __shared__ float t[32][33];
    int nb = blockIdx.x * 32;
    int kb = blockIdx.y * 32;
    int x = threadIdx.x, y = threadIdx.y;   // 32 x 8
#pragma unroll
    for (int yy = y; yy < 32; yy += 8) {
        int k = kb + yy, n = nb + x;
        float v = 0.0f;
        if (k < SIZE_M && n < SIZE_N) v = rna_tf32(src[(size_t)k * SIZE_N + n]);
        t[yy][x] = v;
    }
    __syncthreads();
#pragma unroll
    for (int yy = y; yy < 32; yy += 8) {
        int n = nb + yy, k = kb + x;
        if (n < SIZE_N && k < K_PAD) dst[(size_t)n * K_PAD + k] = t[x][yy];
    }
}

// ============================ host side =====================================

static inline dim3 grid_for(int M, int N) {
    return dim3((N + 127) / 128, (M + 127) / 128);
}

extern "C" void kernel_launch(void* const* d_in, const int* in_sizes, int n_in,
                              void* d_out, int out_size)
{
    const float* x  = (const float*)d_in[0];   // [4096, 2048]
    const float* V1 = (const float*)d_in[1];   // [5794, 2897]
    const float* V2 = (const float*)d_in[2];   // [2897, 5794]
    float* out = (float*)d_out;                // [4096, 2048]

    float *V1r, *V2T, *xr, *Vf, *h1, *h2;
    cudaGetSymbolAddress((void**)&V1r, g_V1r);
    cudaGetSymbolAddress((void**)&V2T, g_V2T);
    cudaGetSymbolAddress((void**)&xr,  g_xr);
    cudaGetSymbolAddress((void**)&Vf,  g_Vf);
    cudaGetSymbolAddress((void**)&h1,  g_h1);
    cudaGetSymbolAddress((void**)&h2,  g_h2);

    round_pad_kernel<<<2048, 256>>>(V1, V1r, SIZE_N, SIZE_M, K_PAD);
    round_pad_kernel<<<2048, 256>>>(x, xr, BATCH, D_IN, D_IN);
    transpose_round_kernel<<<dim3((SIZE_N + 31) / 32, (K_PAD + 31) / 32), dim3(32, 8)>>>(V2, V2T);

    cudaFuncSetAttribute(gemm_mma<false, false, true>,
                         cudaFuncAttributeMaxDynamicSharedMemorySize, SMEM_BYTES);
    cudaFuncSetAttribute(gemm_mma<true, true, true>,
                         cudaFuncAttributeMaxDynamicSharedMemorySize, SMEM_BYTES);
    cudaFuncSetAttribute(gemm_mma<true, false, false>,
                         cudaFuncAttributeMaxDynamicSharedMemorySize, SMEM_BYTES);

    // 1) Vf = V1r @ V2T^T
    gemm_mma<false, false, true><<<grid_for(SIZE_N, SIZE_N), 256, SMEM_BYTES>>>(
        V1r, V2T, nullptr, Vf, SIZE_N, SIZE_N, K_PAD, K_PAD, K_PAD, SIZE_N);

    // 2) h1 = relu(xr @ W1^T + b1)
    gemm_mma<true, true, true><<<grid_for(BATCH, D_H), 256, SMEM_BYTES>>>(
        xr, Vf + OFF_W1, Vf + OFF_B1, h1, BATCH, D_H, D_IN, D_IN, D_IN, D_H);

    // 3) h2 = relu(h1 @ W2^T + b2)
    gemm_mma<true, true, true><<<grid_for(BATCH, D_H), 256, SMEM_BYTES>>>(
        h1, Vf + OFF_W2, Vf + OFF_B2, h2, BATCH, D_H, D_H, D_H, D_H, D_H);

    // 4) out = h2 @ W3^T + b3
    gemm_mma<true, false, false><<<grid_for(BATCH, D_OUT), 256, SMEM_BYTES>>>(
        h2, Vf + OFF_W3, Vf + OFF_B3, out, BATCH, D_OUT, D_H, D_H, D_H, D_OUT);
}

// round 5
// speedup vs baseline: 1.0733x; 1.0733x over previous
#include <cuda_runtime.h>
#include <cuda_bf16.h>
#include <cstdint>

// ---------------------------------------------------------------------------
// FeatherNet via warp-level mma.sync tf32 (generic PTX):
//   Vf = V1@V2 ; h1 = relu(x W1^T + b1); h2 = relu(h1 W2^T + b2); out = h2 W3^T + b3
// All 4 GEMMs NT: C[M,N] = A[M,K] * B[N,K]^T.
// R5: 4 warps / CTA, 64x64 warp tile (LDS/MMA 1.5 -> 1.0), 3-stage ring.
// ---------------------------------------------------------------------------

#define SIZE_N 5794
#define SIZE_M 2897
#define K_PAD  2912        // 91 * 32
#define BATCH  4096
#define D_IN   2048
#define D_H    4096
#define D_OUT  2048

#define OFF_W1 0
#define OFF_B1 8388608
#define OFF_W2 8392704
#define OFF_B2 25169920
#define OFF_W3 25174016
#define OFF_B3 33562624

__device__ __align__(256) float g_V1r[(size_t)SIZE_N * K_PAD];
__device__ __align__(256) float g_V2T[(size_t)SIZE_N * K_PAD];
__device__ __align__(256) float g_xr [(size_t)BATCH * D_IN];
__device__ __align__(256) float g_Vf [(size_t)SIZE_N * SIZE_N];
__device__ __align__(256) float g_h1 [(size_t)BATCH * D_H];
__device__ __align__(256) float g_h2 [(size_t)BATCH * D_H];

// ============================ helpers =======================================

__device__ __forceinline__ float rna_tf32(float v) {
    uint32_t u;
    asm("cvt.rna.tf32.f32 %0, %1;" : "=r"(u) : "f"(v));
    return __uint_as_float(u);
}

__device__ __forceinline__ uint32_t smem_u32(const void* p) {
    uint32_t a;
    asm("{ .reg .u64 t; cvta.to.shared.u64 t, %1; cvt.u32.u64 %0, t; }"
        : "=r"(a) : "l"(p));
    return a;
}

__device__ __forceinline__ void cp_async16(uint32_t dst, const void* src, bool valid) {
    int sz = valid ? 16 : 0;
    asm volatile("cp.async.cg.shared.global [%0], [%1], 16, %2;"
                 :: "r"(dst), "l"(src), "r"(sz) : "memory");
}
#define CP_COMMIT()  asm volatile("cp.async.commit_group;" ::: "memory")
#define CP_WAIT_1()  asm volatile("cp.async.wait_group 1;" ::: "memory")

__device__ __forceinline__ void mma_tf32(float4& d, const uint32_t* a, const uint32_t* b) {
    asm volatile(
        "mma.sync.aligned.m16n8k8.row.col.f32.tf32.tf32.f32 "
        "{%0,%1,%2,%3}, {%4,%5,%6,%7}, {%8,%9}, {%0,%1,%2,%3};"
        : "+f"(d.x), "+f"(d.y), "+f"(d.z), "+f"(d.w)
        : "r"(a[0]), "r"(a[1]), "r"(a[2]), "r"(a[3]), "r"(b[0]), "r"(b[1]));
}

// smem: tile rows of 32 floats (128B), 16B groups XOR-swizzled by row.
__device__ __forceinline__ int sw(int row, int k) {
    return row * 32 + ((((k >> 2) ^ row) & 7) << 2) + (k & 3);
}

// ============================ GEMM kernel ===================================
// 128x128 CTA tile, BK=32, 4 warps (2M x 2N), warp tile 64x64, 3-stage ring.

#define A_TILE_F 4096          // 128 * 32 floats
#define STAGE_F  8192          // A + B
#define NST      3
#define SMEM_BYTES (NST * STAGE_F * 4)

template<bool BIAS, bool RELU, bool ROUND>
__global__ __launch_bounds__(128, 2)
void gemm_mma(const float* __restrict__ A, const float* __restrict__ B,
              const float* __restrict__ bias, float* __restrict__ C,
              int M, int N, int K, int lda, int ldb, int ldc)
{
    extern __shared__ float smf[];
    const uint32_t smem_base = smem_u32(smf);

    const int tid = threadIdx.x;
    const int wid = tid >> 5;
    const int lid = tid & 31;
    const int r   = lid >> 2;     // 0..7
    const int c   = lid & 3;      // 0..3
    const int bm  = blockIdx.y * 128;
    const int bn  = blockIdx.x * 128;
    const int m0  = (wid & 1) * 64;
    const int n0  = (wid >> 1) * 64;

    // loader assignments: 8 chunks of A + 8 of B per thread per stage
    int lrow[8], lcg[8];
#pragma unroll
    for (int i = 0; i < 8; i++) {
        int q = tid + i * 128;        // 0..1023
        lrow[i] = q >> 3;
        lcg[i]  = q & 7;
    }

    float4 acc[4][8];
#pragma unroll
    for (int i = 0; i < 4; i++)
#pragma unroll
        for (int j = 0; j < 8; j++) acc[i][j] = make_float4(0.f, 0.f, 0.f, 0.f);

    const int T = K >> 5;   // K / 32

    auto load_stage = [&](int t, int buf) {
        const int kblk = t * 32;
        uint32_t sA = smem_base + (uint32_t)(buf * STAGE_F) * 4;
        uint32_t sB = sA + A_TILE_F * 4;
#pragma unroll
        for (int i = 0; i < 8; i++) {
            int row = lrow[i], cg = lcg[i];
            int gm = bm + row;
            bool v = gm < M;
            const float* src = A + (size_t)(v ? gm : 0) * lda + kblk + cg * 4;
            cp_async16(sA + (uint32_t)(sw(row, cg * 4)) * 4, src, v);
        }
#pragma unroll
        for (int i = 0; i < 8; i++) {
            int row = lrow[i], cg = lcg[i];
            int gn = bn + row;
            bool v = gn < N;
            const float* src = B + (size_t)(v ? gn : 0) * ldb + kblk + cg * 4;
            cp_async16(sB + (uint32_t)(sw(row, cg * 4)) * 4, src, v);
        }
        CP_COMMIT();
    };

    load_stage(0, 0);
    if (T > 1) load_stage(1, 1); else CP_COMMIT();

    int buf = 0;
    for (int t = 0; t < T; t++) {
        CP_WAIT_1();
        __syncthreads();

        if (t + 2 < T) load_stage(t + 2, (t + 2) % NST);
        else CP_COMMIT();

        const float* As = smf + buf * STAGE_F;
        const float* Bs = As + A_TILE_F;
        const uint32_t* Asu = (const uint32_t*)As;
        const uint32_t* Bsu = (const uint32_t*)Bs;

#pragma unroll
        for (int kc = 0; kc < 4; kc++) {
            const int k0 = kc * 8;
            uint32_t af[4][4], bf[8][2];
#pragma unroll
            for (int i = 0; i < 4; i++) {
                int R = m0 + i * 16 + r;
                af[i][0] = Asu[sw(R,     k0 + c)];
                af[i][1] = Asu[sw(R + 8, k0 + c)];
                af[i][2] = Asu[sw(R,     k0 + c + 4)];
                af[i][3] = Asu[sw(R + 8, k0 + c + 4)];
            }
#pragma unroll
            for (int j = 0; j < 8; j++) {
                int Rb = n0 + j * 8 + r;
                bf[j][0] = Bsu[sw(Rb, k0 + c)];
                bf[j][1] = Bsu[sw(Rb, k0 + c + 4)];
            }
#pragma unroll
            for (int i = 0; i < 4; i++)
#pragma unroll
                for (int j = 0; j < 8; j++)
                    mma_tf32(acc[i][j], af[i], bf[j]);
        }

        buf++;
        if (buf == NST) buf = 0;
    }

    // ---- epilogue ----------------------------------------------------------
#pragma unroll
    for (int i = 0; i < 4; i++) {
        int gm0 = bm + m0 + i * 16 + r;
#pragma unroll
        for (int j = 0; j < 8; j++) {
            int gn = bn + n0 + j * 8 + 2 * c;
            if (gn >= N) continue;
            float b0 = 0.f, b1 = 0.f;
            if (BIAS) { b0 = __ldg(&bias[gn]); b1 = __ldg(&bias[gn + 1]); }
            float4 v = acc[i][j];
            float x0 = v.x + b0, x1 = v.y + b1;
            float y0 = v.z + b0, y1 = v.w + b1;
            if (RELU) {
                x0 = fmaxf(x0, 0.f); x1 = fmaxf(x1, 0.f);
                y0 = fmaxf(y0, 0.f); y1 = fmaxf(y1, 0.f);
            }
            if (ROUND) {
                x0 = rna_tf32(x0); x1 = rna_tf32(x1);
                y0 = rna_tf32(y0); y1 = rna_tf32(y1);
            }
            if (gm0 < M)
                *(float2*)(&C[(size_t)gm0 * ldc + gn]) = make_float2(x0, x1);
            if (gm0 + 8 < M)
                *(float2*)(&C[(size_t)(gm0 + 8) * ldc + gn]) = make_float2(y0, y1);
        }
    }
}

// ============================ prep kernels ==================================

__global__ void round_pad_kernel(const float* __restrict__ src, float* __restrict__ dst,
                                 int rows, int cols, int dstride)
{
    int total = rows * dstride;
    for (int i = blockIdx.x * blockDim.x + threadIdx.x; i < total; i += gridDim.x * blockDim.x) {
        int rr = i / dstride, cc = i - rr * dstride;
        float v = 0.0f;
        if (cc < cols) v = rna_tf32(src[(size_t)rr * cols + cc]);
        dst[i] = v;
    }
}

__global__ void transpose_round_kernel(const float* __restrict__ src, float* __restrict__ dst)
{
    __shared__ float t[32][33];
    int nb = blockIdx.x * 32;
    int kb = blockIdx.y * 32;
    int x = threadIdx.x, y = threadIdx.y;   // 32 x 8
#pragma unroll
    for (int yy = y; yy < 32; yy += 8) {
        int k = kb + yy, n = nb + x;
        float v = 0.0f;
        if (k < SIZE_M && n < SIZE_N) v = rna_tf32(src[(size_t)k * SIZE_N + n]);
        t[yy][x] = v;
    }
    __syncthreads();
#pragma unroll
    for (int yy = y; yy < 32; yy += 8) {
        int n = nb + yy, k = kb + x;
        if (n < SIZE_N && k < K_PAD) dst[(size_t)n * K_PAD + k] = t[x][yy];
    }
}

// ============================ host side =====================================

static inline dim3 grid_for(int M, int N) {
    return dim3((N + 127) / 128, (M + 127) / 128);
}

extern "C" void kernel_launch(void* const* d_in, const int* in_sizes, int n_in,
                              void* d_out, int out_size)
{
    const float* x  = (const float*)d_in[0];   // [4096, 2048]
    const float* V1 = (const float*)d_in[1];   // [5794, 2897]
    const float* V2 = (const float*)d_in[2];   // [2897, 5794]
    float* out = (float*)d_out;                // [4096, 2048]

    float *V1r, *V2T, *xr, *Vf, *h1, *h2;
    cudaGetSymbolAddress((void**)&V1r, g_V1r);
    cudaGetSymbolAddress((void**)&V2T, g_V2T);
    cudaGetSymbolAddress((void**)&xr,  g_xr);
    cudaGetSymbolAddress((void**)&Vf,  g_Vf);
    cudaGetSymbolAddress((void**)&h1,  g_h1);
    cudaGetSymbolAddress((void**)&h2,  g_h2);

    round_pad_kernel<<<2048, 256>>>(V1, V1r, SIZE_N, SIZE_M, K_PAD);
    round_pad_kernel<<<2048, 256>>>(x, xr, BATCH, D_IN, D_IN);
    transpose_round_kernel<<<dim3((SIZE_N + 31) / 32, (K_PAD + 31) / 32), dim3(32, 8)>>>(V2, V2T);

    cudaFuncSetAttribute(gemm_mma<false, false, true>,
                         cudaFuncAttributeMaxDynamicSharedMemorySize, SMEM_BYTES);
    cudaFuncSetAttribute(gemm_mma<true, true, true>,
                         cudaFuncAttributeMaxDynamicSharedMemorySize, SMEM_BYTES);
    cudaFuncSetAttribute(gemm_mma<true, false, false>,
                         cudaFuncAttributeMaxDynamicSharedMemorySize, SMEM_BYTES);

    // 1) Vf = V1r @ V2T^T
    gemm_mma<false, false, true><<<grid_for(SIZE_N, SIZE_N), 128, SMEM_BYTES>>>(
        V1r, V2T, nullptr, Vf, SIZE_N, SIZE_N, K_PAD, K_PAD, K_PAD, SIZE_N);

    // 2) h1 = relu(xr @ W1^T + b1)
    gemm_mma<true, true, true><<<grid_for(BATCH, D_H), 128, SMEM_BYTES>>>(
        xr, Vf + OFF_W1, Vf + OFF_B1, h1, BATCH, D_H, D_IN, D_IN, D_IN, D_H);

    // 3) h2 = relu(h1 @ W2^T + b2)
    gemm_mma<true, true, true><<<grid_for(BATCH, D_H), 128, SMEM_BYTES>>>(
        h1, Vf + OFF_W2, Vf + OFF_B2, h2, BATCH, D_H, D_H, D_H, D_H, D_H);

    // 4) out = h2 @ W3^T + b3
    gemm_mma<true, false, false><<<grid_for(BATCH, D_OUT), 128, SMEM_BYTES>>>(
        h2, Vf + OFF_W3, Vf + OFF_B3, out, BATCH, D_OUT, D_H, D_H, D_H, D_OUT);
}